// round 4
// baseline (speedup 1.0000x reference)
#include <cuda_runtime.h>
#include <cuda_bf16.h>

// Problem constants
#define BSZ   2
#define TLEN  2048
#define NEMBD 1024
#define NHEAD 16
#define HS    64           // head size
#define MASK_VAL (-10.0f)

#define BT (BSZ * TLEN)    // 4096 rows

// Scratch (device globals: no allocations allowed)
__device__ float g_qkv[(size_t)BT * 3 * NEMBD];  // [B*T, 3C]
__device__ float g_y  [(size_t)BT * NEMBD];      // [B*T, C]

// ---------------------------------------------------------------------------
// GEMM: C[M,N] = A[M,K] * B[N,K]^T   (both row-major, K innermost)
// 128x128 tile, BK=8, 256 threads, 8x8 per thread.
// ---------------------------------------------------------------------------
__global__ __launch_bounds__(256) void gemm_nt_kernel(
    const float* __restrict__ A, const float* __restrict__ B,
    float* __restrict__ C, int M, int N, int K)
{
    __shared__ float As[8][128];
    __shared__ float Bs[8][128];

    const int tid = threadIdx.x;
    const int tx = tid & 15;          // 0..15 -> N cols
    const int ty = tid >> 4;          // 0..15 -> M rows
    const int m0 = blockIdx.y * 128;
    const int n0 = blockIdx.x * 128;

    const int lrow = tid >> 1;        // 0..127
    const int lk   = (tid & 1) * 4;   // 0 or 4

    const float* Aptr = A + (size_t)(m0 + lrow) * K + lk;
    const float* Bptr = B + (size_t)(n0 + lrow) * K + lk;

    float acc[8][8];
    #pragma unroll
    for (int i = 0; i < 8; ++i)
        #pragma unroll
        for (int j = 0; j < 8; ++j) acc[i][j] = 0.0f;

    for (int k0 = 0; k0 < K; k0 += 8) {
        float4 av = *(const float4*)(Aptr + k0);
        float4 bv = *(const float4*)(Bptr + k0);
        As[lk + 0][lrow] = av.x; As[lk + 1][lrow] = av.y;
        As[lk + 2][lrow] = av.z; As[lk + 3][lrow] = av.w;
        Bs[lk + 0][lrow] = bv.x; Bs[lk + 1][lrow] = bv.y;
        Bs[lk + 2][lrow] = bv.z; Bs[lk + 3][lrow] = bv.w;
        __syncthreads();

        #pragma unroll
        for (int kk = 0; kk < 8; ++kk) {
            float a[8], b[8];
            float4 a0 = *(const float4*)&As[kk][ty * 8];
            float4 a1 = *(const float4*)&As[kk][ty * 8 + 4];
            float4 b0 = *(const float4*)&Bs[kk][tx * 8];
            float4 b1 = *(const float4*)&Bs[kk][tx * 8 + 4];
            a[0]=a0.x; a[1]=a0.y; a[2]=a0.z; a[3]=a0.w;
            a[4]=a1.x; a[5]=a1.y; a[6]=a1.z; a[7]=a1.w;
            b[0]=b0.x; b[1]=b0.y; b[2]=b0.z; b[3]=b0.w;
            b[4]=b1.x; b[5]=b1.y; b[6]=b1.z; b[7]=b1.w;
            #pragma unroll
            for (int i = 0; i < 8; ++i)
                #pragma unroll
                for (int j = 0; j < 8; ++j)
                    acc[i][j] = fmaf(a[i], b[j], acc[i][j]);
        }
        __syncthreads();
    }

    #pragma unroll
    for (int i = 0; i < 8; ++i) {
        float* Crow = C + (size_t)(m0 + ty * 8 + i) * N + n0 + tx * 8;
        float4 w0 = make_float4(acc[i][0], acc[i][1], acc[i][2], acc[i][3]);
        float4 w1 = make_float4(acc[i][4], acc[i][5], acc[i][6], acc[i][7]);
        *(float4*)(Crow)     = w0;
        *(float4*)(Crow + 4) = w1;
    }
}

// ---------------------------------------------------------------------------
// Attention: per (b,h) head, 64-query tiles, online softmax over ALL 2048
// keys (soft mask value -10, masked keys keep nonzero weight).
// 256 threads: ty=tid/16 owns 4 query rows, tx=tid%16 owns 2 key cols (S)
// and 4 output dims (O).
// ---------------------------------------------------------------------------
__global__ __launch_bounds__(256) void attn_kernel(
    const float* __restrict__ qkv, float* __restrict__ y)
{
    __shared__ float Qs[64][68];  // Qs[d][r], pre-scaled by 1/8
    __shared__ float Ks[64][36];  // Ks[d][c], c = key within 32-tile
    __shared__ float Vs[32][68];  // Vs[c][d]
    __shared__ float Ps[64][36];  // P[r][c]

    const int tid = threadIdx.x;
    const int tx = tid & 15;
    const int ty = tid >> 4;
    const int bh = blockIdx.y;
    const int b = bh / NHEAD;
    const int h = bh % NHEAD;
    const int q0 = blockIdx.x * 64;

    const size_t rowstride = 3 * NEMBD;
    const size_t headoff = (size_t)h * HS;

    // Load Q tile, transposed + pre-scaled
    for (int idx = tid; idx < 64 * 64; idx += 256) {
        int r = idx >> 6, d = idx & 63;
        Qs[d][r] = qkv[(size_t)(b * TLEN + q0 + r) * rowstride + headoff + d] * 0.125f;
    }

    float o[4][4];
    float m_i[4], l_i[4];
    #pragma unroll
    for (int i = 0; i < 4; ++i) {
        m_i[i] = -1e30f; l_i[i] = 0.0f;
        #pragma unroll
        for (int j = 0; j < 4; ++j) o[i][j] = 0.0f;
    }

    for (int kt = 0; kt < TLEN / 32; ++kt) {
        // Load K (transposed) and V tiles
        for (int idx = tid; idx < 32 * 64; idx += 256) {
            int c = idx >> 6, d = idx & 63;
            const float* base = qkv + (size_t)(b * TLEN + kt * 32 + c) * rowstride + headoff;
            Ks[d][c] = base[NEMBD + d];       // K
            Vs[c][d] = base[2 * NEMBD + d];   // V
        }
        __syncthreads();

        // S = Q K^T  (4 rows x 2 cols per thread)
        float s[4][2];
        #pragma unroll
        for (int i = 0; i < 4; ++i) { s[i][0] = 0.0f; s[i][1] = 0.0f; }
        #pragma unroll 8
        for (int d = 0; d < 64; ++d) {
            float4 qv = *(const float4*)&Qs[d][ty * 4];
            float2 kv = *(const float2*)&Ks[d][tx * 2];
            s[0][0] = fmaf(qv.x, kv.x, s[0][0]); s[0][1] = fmaf(qv.x, kv.y, s[0][1]);
            s[1][0] = fmaf(qv.y, kv.x, s[1][0]); s[1][1] = fmaf(qv.y, kv.y, s[1][1]);
            s[2][0] = fmaf(qv.z, kv.x, s[2][0]); s[2][1] = fmaf(qv.z, kv.y, s[2][1]);
            s[3][0] = fmaf(qv.w, kv.x, s[3][0]); s[3][1] = fmaf(qv.w, kv.y, s[3][1]);
        }

        // Soft causal mask: exactly MASK_VAL where k > q
        const int qbase = q0 + ty * 4;
        const int kbase = kt * 32 + tx * 2;
        #pragma unroll
        for (int i = 0; i < 4; ++i)
            #pragma unroll
            for (int j = 0; j < 2; ++j)
                if (kbase + j > qbase + i) s[i][j] = MASK_VAL;

        // Online softmax update per row
        #pragma unroll
        for (int i = 0; i < 4; ++i) {
            float rm = fmaxf(s[i][0], s[i][1]);
            #pragma unroll
            for (int off = 8; off > 0; off >>= 1)
                rm = fmaxf(rm, __shfl_xor_sync(0xffffffffu, rm, off, 16));
            float newm = fmaxf(m_i[i], rm);
            float scl = __expf(m_i[i] - newm);
            m_i[i] = newm;
            float p0 = __expf(s[i][0] - newm);
            float p1 = __expf(s[i][1] - newm);
            float rs = p0 + p1;
            #pragma unroll
            for (int off = 8; off > 0; off >>= 1)
                rs += __shfl_xor_sync(0xffffffffu, rs, off, 16);
            l_i[i] = l_i[i] * scl + rs;
            #pragma unroll
            for (int j = 0; j < 4; ++j) o[i][j] *= scl;
            Ps[ty * 4 + i][tx * 2]     = p0;
            Ps[ty * 4 + i][tx * 2 + 1] = p1;
        }
        __syncthreads();

        // O += P V  (thread: 4 rows x 4 dims)
        #pragma unroll 4
        for (int kk = 0; kk < 32; ++kk) {
            float4 v4 = *(const float4*)&Vs[kk][tx * 4];
            #pragma unroll
            for (int i = 0; i < 4; ++i) {
                float pv = Ps[ty * 4 + i][kk];
                o[i][0] = fmaf(pv, v4.x, o[i][0]);
                o[i][1] = fmaf(pv, v4.y, o[i][1]);
                o[i][2] = fmaf(pv, v4.z, o[i][2]);
                o[i][3] = fmaf(pv, v4.w, o[i][3]);
            }
        }
        __syncthreads();
    }

    // Normalize and write y in [B,T,C] layout (C = h*HS + d)
    #pragma unroll
    for (int i = 0; i < 4; ++i) {
        float inv = 1.0f / l_i[i];
        float* yr = y + (size_t)(b * TLEN + q0 + ty * 4 + i) * NEMBD + headoff + tx * 4;
        float4 w = make_float4(o[i][0] * inv, o[i][1] * inv, o[i][2] * inv, o[i][3] * inv);
        *(float4*)yr = w;
    }
}

// ---------------------------------------------------------------------------
extern "C" void kernel_launch(void* const* d_in, const int* in_sizes, int n_in,
                              void* d_out, int out_size)
{
    const float* x      = (const float*)d_in[0];
    const float* w_attn = (const float*)d_in[1];
    const float* w_proj = (const float*)d_in[2];
    float* out = (float*)d_out;

    float *qkv, *y;
    cudaGetSymbolAddress((void**)&qkv, g_qkv);
    cudaGetSymbolAddress((void**)&y,   g_y);

    // 1) QKV projection: [4096, 3072] = x[4096,1024] @ w_attn^T
    gemm_nt_kernel<<<dim3(3 * NEMBD / 128, BT / 128), 256>>>(
        x, w_attn, qkv, BT, 3 * NEMBD, NEMBD);

    // 2) Attention per (b,h), 64-query tiles
    attn_kernel<<<dim3(TLEN / 64, BSZ * NHEAD), 256>>>(qkv, y);

    // 3) Output projection: [4096, 1024] = y @ w_proj^T
    gemm_nt_kernel<<<dim3(NEMBD / 128, BT / 128), 256>>>(
        y, w_proj, out, BT, NEMBD, NEMBD);
}

// round 6
// speedup vs baseline: 3.3755x; 3.3755x over previous
#include <cuda_runtime.h>
#include <cuda_bf16.h>
#include <cstdint>

// Problem constants
#define BSZ   2
#define TLEN  2048
#define NEMBD 1024
#define NHEAD 16
#define HS    64
#define MASK_VAL (-10.0f)
#define BT (BSZ * TLEN)       // 4096
#define C3 (3 * NEMBD)        // 3072
#define NBH (BSZ * NHEAD)     // 32
#define NTILE (TLEN / 64)     // 32 key tiles of 64

// Scratch (device globals: no allocations allowed)
__device__ float g_qkv [(size_t)BT * C3];       // [B*T, 3C]
__device__ float g_y   [(size_t)BT * NEMBD];    // [B*T, C]
__device__ float g_vsuf[(size_t)NBH * (NTILE + 1) * HS]; // suffix V sums per 64-key tile

// ---------------------------------------------------------------------------
// helpers
// ---------------------------------------------------------------------------
__device__ __forceinline__ uint32_t f2tf32(float x) {
    uint32_t r;
    asm("cvt.rna.tf32.f32 %0, %1;" : "=r"(r) : "f"(x));
    return r;
}

__device__ __forceinline__ void mma8(float* c, const uint32_t* a, const uint32_t* b) {
    asm volatile(
        "mma.sync.aligned.m16n8k8.row.col.f32.tf32.tf32.f32 "
        "{%0,%1,%2,%3}, {%4,%5,%6,%7}, {%8,%9}, {%0,%1,%2,%3};\n"
        : "+f"(c[0]), "+f"(c[1]), "+f"(c[2]), "+f"(c[3])
        : "r"(a[0]), "r"(a[1]), "r"(a[2]), "r"(a[3]),
          "r"(b[0]), "r"(b[1]));
}

// ---------------------------------------------------------------------------
// GEMM: C[M,N] = A[M,K] * B[N,K]^T  via mma.sync tf32.
// Block 128x128, BK=32, 256 threads = 8 warps (2 along M x 4 along N),
// warp tile 64x32 = 4x4 m16n8k8 tiles.
// smem layout [row][36] (pad 4): frag loads (4m+k)%32 all distinct -> no conflicts.
// ---------------------------------------------------------------------------
__global__ __launch_bounds__(256) void gemm_tf32(
    const float* __restrict__ A, const float* __restrict__ B,
    float* __restrict__ Cmat, int M, int N, int K)
{
    __shared__ uint32_t As[128 * 36];
    __shared__ uint32_t Bs[128 * 36];

    const int tid  = threadIdx.x;
    const int lane = tid & 31;
    const int warp = tid >> 5;
    const int wm   = warp >> 2;       // 0..1
    const int wn   = warp & 3;        // 0..3
    const int m0   = blockIdx.y * 128;
    const int n0   = blockIdx.x * 128;

    const int lrow = tid >> 1;        // 0..127
    const int lcol = (tid & 1) * 16;  // 0 or 16

    const float* Ap = A + (size_t)(m0 + lrow) * K + lcol;
    const float* Bp = B + (size_t)(n0 + lrow) * K + lcol;

    float acc[4][4][4];
    #pragma unroll
    for (int i = 0; i < 4; ++i)
        #pragma unroll
        for (int j = 0; j < 4; ++j)
            #pragma unroll
            for (int c = 0; c < 4; ++c) acc[i][j][c] = 0.0f;

    for (int kb = 0; kb < K; kb += 32) {
        #pragma unroll
        for (int j = 0; j < 4; ++j) {
            float4 av = *(const float4*)(Ap + kb + 4 * j);
            float4 bv = *(const float4*)(Bp + kb + 4 * j);
            uint32_t* as = &As[lrow * 36 + lcol + 4 * j];
            uint32_t* bs = &Bs[lrow * 36 + lcol + 4 * j];
            as[0] = f2tf32(av.x); as[1] = f2tf32(av.y);
            as[2] = f2tf32(av.z); as[3] = f2tf32(av.w);
            bs[0] = f2tf32(bv.x); bs[1] = f2tf32(bv.y);
            bs[2] = f2tf32(bv.z); bs[3] = f2tf32(bv.w);
        }
        __syncthreads();

        #pragma unroll
        for (int ks = 0; ks < 4; ++ks) {
            const int k0 = ks * 8;
            uint32_t af[4][4], bf[4][2];
            #pragma unroll
            for (int i = 0; i < 4; ++i) {
                const int mb = wm * 64 + i * 16 + (lane >> 2);
                af[i][0] = As[mb * 36 + k0 + (lane & 3)];
                af[i][1] = As[(mb + 8) * 36 + k0 + (lane & 3)];
                af[i][2] = As[mb * 36 + k0 + 4 + (lane & 3)];
                af[i][3] = As[(mb + 8) * 36 + k0 + 4 + (lane & 3)];
            }
            #pragma unroll
            for (int j = 0; j < 4; ++j) {
                const int nb = wn * 32 + j * 8 + (lane >> 2);
                bf[j][0] = Bs[nb * 36 + k0 + (lane & 3)];
                bf[j][1] = Bs[nb * 36 + k0 + 4 + (lane & 3)];
            }
            #pragma unroll
            for (int i = 0; i < 4; ++i)
                #pragma unroll
                for (int j = 0; j < 4; ++j)
                    mma8(acc[i][j], af[i], bf[j]);
        }
        __syncthreads();
    }

    // Epilogue: C fragment layout (row=lane>>2(+8), col=2*(lane&3)(+1))
    #pragma unroll
    for (int i = 0; i < 4; ++i) {
        const int row0 = m0 + wm * 64 + i * 16 + (lane >> 2);
        #pragma unroll
        for (int j = 0; j < 4; ++j) {
            const int col = n0 + wn * 32 + j * 8 + 2 * (lane & 3);
            *(float2*)&Cmat[(size_t)row0 * N + col] =
                make_float2(acc[i][j][0], acc[i][j][1]);
            *(float2*)&Cmat[(size_t)(row0 + 8) * N + col] =
                make_float2(acc[i][j][2], acc[i][j][3]);
        }
    }
}

// ---------------------------------------------------------------------------
// V suffix sums at 64-key-tile granularity.
// pass 1: per-(bh, tile) partial sums of 64 V rows.
// pass 2: in-place suffix scan over 32 tiles (+ zero sentinel tile 32).
// ---------------------------------------------------------------------------
__global__ void vsuf_partial(const float* __restrict__ qkv) {
    const int t  = blockIdx.x;          // 0..31
    const int bh = blockIdx.y;          // 0..31
    const int b = bh >> 4, h = bh & 15;
    const int d = threadIdx.x;          // 0..63
    float s = 0.0f;
    const float* base = qkv + (size_t)(b * TLEN + t * 64) * C3 + 2 * NEMBD + h * HS + d;
    #pragma unroll 8
    for (int r = 0; r < 64; ++r) s += base[(size_t)r * C3];
    g_vsuf[((size_t)bh * (NTILE + 1) + t) * HS + d] = s;
}

__global__ void vsuf_suffix() {
    const int bh = blockIdx.x;
    const int d  = threadIdx.x;
    float* p = g_vsuf + (size_t)bh * (NTILE + 1) * HS + d;
    p[(size_t)NTILE * HS] = 0.0f;   // sentinel: no keys beyond T
    float run = 0.0f;
    for (int t = NTILE - 1; t >= 0; --t) {
        run += p[(size_t)t * HS];
        p[(size_t)t * HS] = run;    // suffix inclusive of tile t
    }
}

// ---------------------------------------------------------------------------
// Attention (tensor-core, causal-skip):
// grid (32 qblocks x 32 bh), 128 threads = 4 warps; warp owns 16 query rows.
// Only key tiles kt <= qblk are processed. Strictly-future keys contribute a
// uniform weight e^(MASK_VAL - m) times the precomputed V suffix sum.
// Online softmax kept in C-fragment layout; P goes through smem as tf32.
// ---------------------------------------------------------------------------
__global__ __launch_bounds__(128) void attn_mma(
    const float* __restrict__ qkv, float* __restrict__ y)
{
    extern __shared__ float sm[];
    float* Qs = sm;                  // [64][68] tf32 bits (Q * 1/8)
    float* Ks = Qs + 64 * 68;        // [64 keys][68 d] tf32 bits (also vsuf stage)
    float* Vs = Ks + 64 * 68;        // [64 keys][68 d] tf32 bits
    float* Ps = Vs + 64 * 68;        // [64 q][68 keys] tf32 bits

    const int tid  = threadIdx.x;
    const int lane = tid & 31;
    const int w    = tid >> 5;                 // warp id: rows w*16..w*16+15
    const int bh   = blockIdx.y;
    const int b = bh >> 4, h = bh & 15;
    const int qblk = gridDim.x - 1 - blockIdx.x;  // heaviest blocks first
    const int q0   = qblk * 64;

    const int qr = (lane >> 2);                // fragment row within 16 (and +8)
    const int c4 = (lane & 3);                 // fragment col group

    // Load Q tile (scaled by 1/sqrt(hs)=0.125, tf32)
    for (int idx = tid; idx < 64 * 16; idx += 128) {
        const int r = idx >> 4, dq = (idx & 15) * 4;
        float4 v = *(const float4*)(qkv + (size_t)(b * TLEN + q0 + r) * C3 + h * HS + dq);
        uint32_t* dst = (uint32_t*)&Qs[r * 68 + dq];
        dst[0] = f2tf32(v.x * 0.125f); dst[1] = f2tf32(v.y * 0.125f);
        dst[2] = f2tf32(v.z * 0.125f); dst[3] = f2tf32(v.w * 0.125f);
    }

    float oacc[8][4];
    #pragma unroll
    for (int j = 0; j < 8; ++j)
        #pragma unroll
        for (int c = 0; c < 4; ++c) oacc[j][c] = 0.0f;
    float mA = MASK_VAL, mB = MASK_VAL;   // init to mask value: shift-consistent
    float lA = 0.0f, lB = 0.0f;

    __syncthreads();

    for (int kt = 0; kt <= qblk; ++kt) {
        // Cooperative load of K and V tiles (tf32)
        for (int idx = tid; idx < 64 * 16; idx += 128) {
            const int r = idx >> 4, dq = (idx & 15) * 4;
            const float* base = qkv + (size_t)(b * TLEN + kt * 64 + r) * C3 + h * HS;
            float4 kv = *(const float4*)(base + NEMBD + dq);
            float4 vv = *(const float4*)(base + 2 * NEMBD + dq);
            uint32_t* kd = (uint32_t*)&Ks[r * 68 + dq];
            uint32_t* vd = (uint32_t*)&Vs[r * 68 + dq];
            kd[0] = f2tf32(kv.x); kd[1] = f2tf32(kv.y);
            kd[2] = f2tf32(kv.z); kd[3] = f2tf32(kv.w);
            vd[0] = f2tf32(vv.x); vd[1] = f2tf32(vv.y);
            vd[2] = f2tf32(vv.z); vd[3] = f2tf32(vv.w);
        }
        __syncthreads();

        // S[16 x 64] = Q_warp * K^T   (8 key n-tiles, 8 d k-steps)
        float sacc[8][4];
        #pragma unroll
        for (int j = 0; j < 8; ++j)
            #pragma unroll
            for (int c = 0; c < 4; ++c) sacc[j][c] = 0.0f;

        const uint32_t* Qu = (const uint32_t*)Qs;
        const uint32_t* Ku = (const uint32_t*)Ks;
        const uint32_t* Vu = (const uint32_t*)Vs;
        const uint32_t* Pu = (const uint32_t*)Ps;

        #pragma unroll
        for (int ks = 0; ks < 8; ++ks) {
            const int k0 = ks * 8;
            uint32_t af[4];
            const int mb = w * 16 + qr;
            af[0] = Qu[mb * 68 + k0 + c4];
            af[1] = Qu[(mb + 8) * 68 + k0 + c4];
            af[2] = Qu[mb * 68 + k0 + 4 + c4];
            af[3] = Qu[(mb + 8) * 68 + k0 + 4 + c4];
            #pragma unroll
            for (int j = 0; j < 8; ++j) {
                uint32_t bf[2];
                bf[0] = Ku[(j * 8 + qr) * 68 + k0 + c4];
                bf[1] = Ku[(j * 8 + qr) * 68 + k0 + 4 + c4];
                mma8(sacc[j], af, bf);
            }
        }

        // Soft causal mask on the diagonal tile only
        if (kt == qblk) {
            const int qrowA = w * 16 + qr, qrowB = qrowA + 8;
            #pragma unroll
            for (int j = 0; j < 8; ++j) {
                const int kc = j * 8 + 2 * c4;
                if (kc     > qrowA) sacc[j][0] = MASK_VAL;
                if (kc + 1 > qrowA) sacc[j][1] = MASK_VAL;
                if (kc     > qrowB) sacc[j][2] = MASK_VAL;
                if (kc + 1 > qrowB) sacc[j][3] = MASK_VAL;
            }
        }

        // Online softmax (rows qrA = w*16+qr, qrB = +8; cols spread over lane&3)
        float rmA = sacc[0][0], rmB = sacc[0][2];
        #pragma unroll
        for (int j = 0; j < 8; ++j) {
            rmA = fmaxf(rmA, fmaxf(sacc[j][0], sacc[j][1]));
            rmB = fmaxf(rmB, fmaxf(sacc[j][2], sacc[j][3]));
        }
        rmA = fmaxf(rmA, __shfl_xor_sync(0xffffffffu, rmA, 1));
        rmA = fmaxf(rmA, __shfl_xor_sync(0xffffffffu, rmA, 2));
        rmB = fmaxf(rmB, __shfl_xor_sync(0xffffffffu, rmB, 1));
        rmB = fmaxf(rmB, __shfl_xor_sync(0xffffffffu, rmB, 2));

        const float nmA = fmaxf(mA, rmA), nmB = fmaxf(mB, rmB);
        const float sclA = __expf(mA - nmA), sclB = __expf(mB - nmB);
        mA = nmA; mB = nmB;

        float psA = 0.0f, psB = 0.0f;
        const int prA = (w * 16 + qr) * 68, prB = prA + 8 * 68;
        #pragma unroll
        for (int j = 0; j < 8; ++j) {
            const int kc = j * 8 + 2 * c4;
            float p0 = __expf(sacc[j][0] - mA);
            float p1 = __expf(sacc[j][1] - mA);
            float p2 = __expf(sacc[j][2] - mB);
            float p3 = __expf(sacc[j][3] - mB);
            psA += p0 + p1; psB += p2 + p3;
            ((uint32_t*)Ps)[prA + kc]     = f2tf32(p0);
            ((uint32_t*)Ps)[prA + kc + 1] = f2tf32(p1);
            ((uint32_t*)Ps)[prB + kc]     = f2tf32(p2);
            ((uint32_t*)Ps)[prB + kc + 1] = f2tf32(p3);
            oacc[j][0] *= sclA; oacc[j][1] *= sclA;
            oacc[j][2] *= sclB; oacc[j][3] *= sclB;
        }
        psA += __shfl_xor_sync(0xffffffffu, psA, 1);
        psA += __shfl_xor_sync(0xffffffffu, psA, 2);
        psB += __shfl_xor_sync(0xffffffffu, psB, 1);
        psB += __shfl_xor_sync(0xffffffffu, psB, 2);
        lA = lA * sclA + psA;
        lB = lB * sclB + psB;
        __syncwarp();

        // O += P * V   (8 key k-steps, 8 d n-tiles)
        #pragma unroll
        for (int ks = 0; ks < 8; ++ks) {
            const int k0 = ks * 8;
            uint32_t af[4];
            const int mb = w * 16 + qr;
            af[0] = Pu[mb * 68 + k0 + c4];
            af[1] = Pu[(mb + 8) * 68 + k0 + c4];
            af[2] = Pu[mb * 68 + k0 + 4 + c4];
            af[3] = Pu[(mb + 8) * 68 + k0 + 4 + c4];
            #pragma unroll
            for (int j = 0; j < 8; ++j) {
                uint32_t bf[2];
                bf[0] = Vu[(k0 + c4) * 68 + j * 8 + qr];
                bf[1] = Vu[(k0 + 4 + c4) * 68 + j * 8 + qr];
                mma8(oacc[j], af, bf);
            }
        }
        __syncthreads();   // protect Ks/Vs before next tile load
    }

    // Closed-form tail for all strictly-future keys (uniform weight e^(-10-m))
    const int nmask = TLEN - 64 * (qblk + 1);
    for (int d = tid; d < HS; d += 128)
        Ks[d] = g_vsuf[((size_t)bh * (NTILE + 1) + qblk + 1) * HS + d];
    __syncthreads();

    const float wtA = __expf(MASK_VAL - mA);
    const float wtB = __expf(MASK_VAL - mB);
    lA += (float)nmask * wtA;
    lB += (float)nmask * wtB;
    const float invA = 1.0f / lA, invB = 1.0f / lB;

    const int rowA = b * TLEN + q0 + w * 16 + qr;
    float* yA = y + (size_t)rowA * NEMBD + h * HS;
    float* yB = y + (size_t)(rowA + 8) * NEMBD + h * HS;
    #pragma unroll
    for (int j = 0; j < 8; ++j) {
        const int d0 = j * 8 + 2 * c4;
        const float v0 = Ks[d0], v1 = Ks[d0 + 1];
        *(float2*)&yA[d0] = make_float2((oacc[j][0] + wtA * v0) * invA,
                                        (oacc[j][1] + wtA * v1) * invA);
        *(float2*)&yB[d0] = make_float2((oacc[j][2] + wtB * v0) * invB,
                                        (oacc[j][3] + wtB * v1) * invB);
    }
}

// ---------------------------------------------------------------------------
extern "C" void kernel_launch(void* const* d_in, const int* in_sizes, int n_in,
                              void* d_out, int out_size)
{
    const float* x      = (const float*)d_in[0];
    const float* w_attn = (const float*)d_in[1];
    const float* w_proj = (const float*)d_in[2];
    float* out = (float*)d_out;

    float *qkv, *y;
    cudaGetSymbolAddress((void**)&qkv, g_qkv);
    cudaGetSymbolAddress((void**)&y,   g_y);

    const int attn_smem = 4 * 64 * 68 * (int)sizeof(float);  // 69632 B
    cudaFuncSetAttribute(attn_mma, cudaFuncAttributeMaxDynamicSharedMemorySize,
                         attn_smem);

    // 1) QKV projection: [4096, 3072] = x @ w_attn^T
    gemm_tf32<<<dim3(C3 / 128, BT / 128), 256>>>(x, w_attn, qkv, BT, C3, NEMBD);

    // 2) V suffix sums (64-key tiles) for the soft-mask closed form
    vsuf_partial<<<dim3(NTILE, NBH), 64>>>(qkv);
    vsuf_suffix<<<NBH, 64>>>();

    // 3) Attention (causal part only + suffix tail)
    attn_mma<<<dim3(NTILE, NBH), 128, attn_smem>>>(qkv, y);

    // 4) Output projection: [4096, 1024] = y @ w_proj^T
    gemm_tf32<<<dim3(NEMBD / 128, BT / 128), 256>>>(y, w_proj, out, BT, NEMBD, NEMBD);
}

// round 7
// speedup vs baseline: 3.6277x; 1.0747x over previous
#include <cuda_runtime.h>
#include <cstdint>

// Problem constants
#define BSZ   2
#define TLEN  2048
#define NEMBD 1024
#define NHEAD 16
#define HS    64
#define MASK_VAL (-10.0f)
#define EMASK   4.5399929762484854e-05f   // exp(-10), exact weight of masked keys
#define BT (BSZ * TLEN)       // 4096
#define C3 (3 * NEMBD)        // 3072
#define NBH (BSZ * NHEAD)     // 32
#define NT64 (TLEN / 64)      // 32 key tiles of 64

// Scratch (device globals: no allocations allowed)
__device__ float g_qkv [(size_t)BT * C3];
__device__ float g_y   [(size_t)BT * NEMBD];
__device__ float g_vsuf[(size_t)NBH * (NT64 + 1) * HS];

// ---------------------------------------------------------------------------
// helpers
// ---------------------------------------------------------------------------
__device__ __forceinline__ uint32_t f2tf32(float x) {
    uint32_t r;
    asm("cvt.rna.tf32.f32 %0, %1;" : "=r"(r) : "f"(x));
    return r;
}

__device__ __forceinline__ void mma8(float* c, const uint32_t* a, const uint32_t* b) {
    asm volatile(
        "mma.sync.aligned.m16n8k8.row.col.f32.tf32.tf32.f32 "
        "{%0,%1,%2,%3}, {%4,%5,%6,%7}, {%8,%9}, {%0,%1,%2,%3};\n"
        : "+f"(c[0]), "+f"(c[1]), "+f"(c[2]), "+f"(c[3])
        : "r"(a[0]), "r"(a[1]), "r"(a[2]), "r"(a[3]),
          "r"(b[0]), "r"(b[1]));
}

// 4x (8 rows x 16B) matrices; for tf32 b32 data thread lane gets element
// (row = lane/4, col32 = lane%4) of each matrix.
__device__ __forceinline__ void ldsm4(uint32_t* r, uint32_t addr) {
    asm volatile("ldmatrix.sync.aligned.m8n8.x4.shared.b16 {%0,%1,%2,%3}, [%4];"
                 : "=r"(r[0]), "=r"(r[1]), "=r"(r[2]), "=r"(r[3]) : "r"(addr));
}

// ---------------------------------------------------------------------------
// GEMM: C[M,N] = A[M,K] * B[N,K]^T  via mma.sync tf32.
// 128x128 block, BK=16, 2-stage smem double buffer + register prefetch.
// 256 threads = 8 warps (2M x 4N), warp tile 64x32.
// smem row stride 20 words (80B): LDSM 8-row reads conflict-free.
// ---------------------------------------------------------------------------
#define GSW 20
__global__ __launch_bounds__(256) void gemm_tf32(
    const float* __restrict__ A, const float* __restrict__ B,
    float* __restrict__ Cmat, int M, int N, int K)
{
    __shared__ uint32_t As[2][128 * GSW];
    __shared__ uint32_t Bs[2][128 * GSW];

    const int tid  = threadIdx.x;
    const int lane = tid & 31;
    const int warp = tid >> 5;
    const int wm   = warp >> 2;
    const int wn   = warp & 3;
    const int m0   = blockIdx.y * 128;
    const int n0   = blockIdx.x * 128;

    const int lrow = tid >> 1;
    const int lk8  = (tid & 1) * 8;

    const float* Ap = A + (size_t)(m0 + lrow) * K + lk8;
    const float* Bp = B + (size_t)(n0 + lrow) * K + lk8;

    // ldmatrix lane address components
    const int ar = lane & 15;                 // A-frag row offset (within 16)
    const int ac = (lane >> 4) * 4;           // A-frag col offset
    const int br = ((lane >> 4) << 3) + (lane & 7);  // B-frag row offset (within 16)
    const int bc = ((lane >> 3) & 1) * 4;     // B-frag col offset

    const uint32_t sA = (uint32_t)__cvta_generic_to_shared(&As[0][0]);
    const uint32_t sB = (uint32_t)__cvta_generic_to_shared(&Bs[0][0]);
    const int stwords = 128 * GSW;

    float acc[4][4][4];
    #pragma unroll
    for (int i = 0; i < 4; ++i)
        #pragma unroll
        for (int j = 0; j < 4; ++j)
            #pragma unroll
            for (int c = 0; c < 4; ++c) acc[i][j][c] = 0.0f;

    // prologue: load kb=0, store stage 0
    float4 ra0 = *(const float4*)(Ap);
    float4 ra1 = *(const float4*)(Ap + 4);
    float4 rb0 = *(const float4*)(Bp);
    float4 rb1 = *(const float4*)(Bp + 4);
    {
        uint32_t* pa = &As[0][lrow * GSW + lk8];
        uint32_t* pb = &Bs[0][lrow * GSW + lk8];
        *(uint4*)pa       = make_uint4(f2tf32(ra0.x), f2tf32(ra0.y), f2tf32(ra0.z), f2tf32(ra0.w));
        *(uint4*)(pa + 4) = make_uint4(f2tf32(ra1.x), f2tf32(ra1.y), f2tf32(ra1.z), f2tf32(ra1.w));
        *(uint4*)pb       = make_uint4(f2tf32(rb0.x), f2tf32(rb0.y), f2tf32(rb0.z), f2tf32(rb0.w));
        *(uint4*)(pb + 4) = make_uint4(f2tf32(rb1.x), f2tf32(rb1.y), f2tf32(rb1.z), f2tf32(rb1.w));
    }
    __syncthreads();

    const int NKB = K / 16;
    int st = 0;
    for (int kb = 0; kb < NKB; ++kb) {
        if (kb + 1 < NKB) {
            const float* ap = Ap + (kb + 1) * 16;
            const float* bp = Bp + (kb + 1) * 16;
            ra0 = *(const float4*)(ap);
            ra1 = *(const float4*)(ap + 4);
            rb0 = *(const float4*)(bp);
            rb1 = *(const float4*)(bp + 4);
        }

        const uint32_t so = (uint32_t)(st * stwords) * 4u;
        #pragma unroll
        for (int ks = 0; ks < 2; ++ks) {
            const int k0 = ks * 8;
            uint32_t af[4][4], bf[4][2];
            #pragma unroll
            for (int i = 0; i < 4; ++i)
                ldsm4(af[i], sA + so + (uint32_t)((wm * 64 + i * 16 + ar) * GSW + k0 + ac) * 4u);
            #pragma unroll
            for (int jp = 0; jp < 2; ++jp) {
                uint32_t r[4];
                ldsm4(r, sB + so + (uint32_t)((wn * 32 + jp * 16 + br) * GSW + k0 + bc) * 4u);
                bf[2 * jp][0] = r[0]; bf[2 * jp][1] = r[1];
                bf[2 * jp + 1][0] = r[2]; bf[2 * jp + 1][1] = r[3];
            }
            #pragma unroll
            for (int i = 0; i < 4; ++i)
                #pragma unroll
                for (int j = 0; j < 4; ++j)
                    mma8(acc[i][j], af[i], bf[j]);
        }

        if (kb + 1 < NKB) {
            uint32_t* pa = &As[st ^ 1][lrow * GSW + lk8];
            uint32_t* pb = &Bs[st ^ 1][lrow * GSW + lk8];
            *(uint4*)pa       = make_uint4(f2tf32(ra0.x), f2tf32(ra0.y), f2tf32(ra0.z), f2tf32(ra0.w));
            *(uint4*)(pa + 4) = make_uint4(f2tf32(ra1.x), f2tf32(ra1.y), f2tf32(ra1.z), f2tf32(ra1.w));
            *(uint4*)pb       = make_uint4(f2tf32(rb0.x), f2tf32(rb0.y), f2tf32(rb0.z), f2tf32(rb0.w));
            *(uint4*)(pb + 4) = make_uint4(f2tf32(rb1.x), f2tf32(rb1.y), f2tf32(rb1.z), f2tf32(rb1.w));
        }
        __syncthreads();
        st ^= 1;
    }

    #pragma unroll
    for (int i = 0; i < 4; ++i) {
        const int row0 = m0 + wm * 64 + i * 16 + (lane >> 2);
        #pragma unroll
        for (int j = 0; j < 4; ++j) {
            const int col = n0 + wn * 32 + j * 8 + 2 * (lane & 3);
            *(float2*)&Cmat[(size_t)row0 * N + col] =
                make_float2(acc[i][j][0], acc[i][j][1]);
            *(float2*)&Cmat[(size_t)(row0 + 8) * N + col] =
                make_float2(acc[i][j][2], acc[i][j][3]);
        }
    }
}

// ---------------------------------------------------------------------------
// V suffix sums at 64-key-tile granularity (for the soft-mask closed form).
// ---------------------------------------------------------------------------
__global__ void vsuf_partial(const float* __restrict__ qkv) {
    const int t  = blockIdx.x;
    const int bh = blockIdx.y;
    const int b = bh >> 4, h = bh & 15;
    const int d = threadIdx.x;
    float s = 0.0f;
    const float* base = qkv + (size_t)(b * TLEN + t * 64) * C3 + 2 * NEMBD + h * HS + d;
    #pragma unroll 8
    for (int r = 0; r < 64; ++r) s += base[(size_t)r * C3];
    g_vsuf[((size_t)bh * (NT64 + 1) + t) * HS + d] = s;
}

__global__ void vsuf_suffix() {
    const int bh = blockIdx.x;
    const int d  = threadIdx.x;
    float* p = g_vsuf + (size_t)bh * (NT64 + 1) * HS + d;
    p[(size_t)NT64 * HS] = 0.0f;
    float run = 0.0f;
    for (int t = NT64 - 1; t >= 0; --t) {
        run += p[(size_t)t * HS];
        p[(size_t)t * HS] = run;
    }
}

// ---------------------------------------------------------------------------
// Attention v2:
// grid (16 q-blocks of 128 x 32 bh), 128 threads = 4 warps, 32 q-rows/warp.
// Fixed-shift softmax (shift 0): no max tracking, no O rescale; masked keys
// weigh exactly EMASK; strictly-future keys folded in via V suffix sums.
// All fragments via ldmatrix.x4. V stored d-major in smem for B-frag loads.
// smem stride 68 words (272B == 16 mod 128): conflict-free LDSM.
// ---------------------------------------------------------------------------
#define ASW 68
__global__ __launch_bounds__(128) void attn_mma(
    const float* __restrict__ qkv, float* __restrict__ y)
{
    extern __shared__ float sm[];
    float* Qs = sm;                   // [128][68] tf32 (Q * 0.125)
    float* Ks = Qs + 128 * ASW;       // [64 keys][68 d] tf32 (also vsuf stage)
    float* Vt = Ks + 64 * ASW;        // [64 d][68 keys] tf32 (transposed V)
    float* Ps = Vt + 64 * ASW;        // [128 q][68 keys] tf32

    const int tid  = threadIdx.x;
    const int lane = tid & 31;
    const int w    = tid >> 5;
    const int bh   = blockIdx.y;
    const int b = bh >> 4, h = bh & 15;
    const int qblk = gridDim.x - 1 - blockIdx.x;   // heavy first
    const int q0   = qblk * 128;
    const int ktmax = 2 * qblk + 1;

    const int qr = lane >> 2;
    const int c4 = lane & 3;
    const int ar = lane & 15;
    const int ac = (lane >> 4) * 4;
    const int br = ((lane >> 4) << 3) + (lane & 7);
    const int bc = ((lane >> 3) & 1) * 4;

    const uint32_t sQ = (uint32_t)__cvta_generic_to_shared(Qs);
    const uint32_t sK = (uint32_t)__cvta_generic_to_shared(Ks);
    const uint32_t sV = (uint32_t)__cvta_generic_to_shared(Vt);
    const uint32_t sP = (uint32_t)__cvta_generic_to_shared(Ps);
    uint32_t* Psu = (uint32_t*)Ps;

    // Load Q tile (128 rows, scaled by 1/sqrt(64))
    for (int idx = tid; idx < 128 * 16; idx += 128) {
        const int r = idx >> 4, dq = (idx & 15) * 4;
        float4 v = *(const float4*)(qkv + (size_t)(b * TLEN + q0 + r) * C3 + h * HS + dq);
        *(uint4*)&Qs[r * ASW + dq] =
            make_uint4(f2tf32(v.x * 0.125f), f2tf32(v.y * 0.125f),
                       f2tf32(v.z * 0.125f), f2tf32(v.w * 0.125f));
    }

    float oacc[2][8][4];
    #pragma unroll
    for (int mt = 0; mt < 2; ++mt)
        #pragma unroll
        for (int j = 0; j < 8; ++j)
            #pragma unroll
            for (int c = 0; c < 4; ++c) oacc[mt][j][c] = 0.0f;
    float lsum[2][2] = {{0.0f, 0.0f}, {0.0f, 0.0f}};

    for (int kt = 0; kt <= ktmax; ++kt) {
        // K tile: coalesced, row = key
        for (int idx = tid; idx < 64 * 16; idx += 128) {
            const int r = idx >> 4, dq = (idx & 15) * 4;
            float4 kv = *(const float4*)(qkv + (size_t)(b * TLEN + kt * 64 + r) * C3
                                         + NEMBD + h * HS + dq);
            *(uint4*)&Ks[r * ASW + dq] =
                make_uint4(f2tf32(kv.x), f2tf32(kv.y), f2tf32(kv.z), f2tf32(kv.w));
        }
        // V tile transposed: lane = key (conflict-free STS; 16B gmem granularity)
        for (int idx = tid; idx < 64 * 16; idx += 128) {
            const int key = idx & 63, d0 = (idx >> 6) * 4;
            float4 vv = *(const float4*)(qkv + (size_t)(b * TLEN + kt * 64 + key) * C3
                                         + 2 * NEMBD + h * HS + d0);
            ((uint32_t*)Vt)[(d0 + 0) * ASW + key] = f2tf32(vv.x);
            ((uint32_t*)Vt)[(d0 + 1) * ASW + key] = f2tf32(vv.y);
            ((uint32_t*)Vt)[(d0 + 2) * ASW + key] = f2tf32(vv.z);
            ((uint32_t*)Vt)[(d0 + 3) * ASW + key] = f2tf32(vv.w);
        }
        __syncthreads();

        // S = Q K^T : warp rows w*32..w*32+31, all 64 keys
        float sacc[2][8][4];
        #pragma unroll
        for (int mt = 0; mt < 2; ++mt)
            #pragma unroll
            for (int j = 0; j < 8; ++j)
                #pragma unroll
                for (int c = 0; c < 4; ++c) sacc[mt][j][c] = 0.0f;

        #pragma unroll
        for (int ks = 0; ks < 8; ++ks) {
            const int k0 = ks * 8;
            uint32_t af[2][4], bf[8][2];
            #pragma unroll
            for (int mt = 0; mt < 2; ++mt)
                ldsm4(af[mt], sQ + (uint32_t)((w * 32 + mt * 16 + ar) * ASW + k0 + ac) * 4u);
            #pragma unroll
            for (int jp = 0; jp < 4; ++jp) {
                uint32_t r[4];
                ldsm4(r, sK + (uint32_t)((jp * 16 + br) * ASW + k0 + bc) * 4u);
                bf[2 * jp][0] = r[0]; bf[2 * jp][1] = r[1];
                bf[2 * jp + 1][0] = r[2]; bf[2 * jp + 1][1] = r[3];
            }
            #pragma unroll
            for (int mt = 0; mt < 2; ++mt)
                #pragma unroll
                for (int j = 0; j < 8; ++j)
                    mma8(sacc[mt][j], af[mt], bf[j]);
        }

        // Fixed-shift softmax weights + P store (tf32)
        const bool domask = (kt >= ktmax - 1);
        #pragma unroll
        for (int mt = 0; mt < 2; ++mt) {
            const int rl = w * 32 + mt * 16 + qr;   // local row (A half)
            const int rgA = q0 + rl, rgB = rgA + 8;
            #pragma unroll
            for (int j = 0; j < 8; ++j) {
                float p0 = __expf(sacc[mt][j][0]);
                float p1 = __expf(sacc[mt][j][1]);
                float p2 = __expf(sacc[mt][j][2]);
                float p3 = __expf(sacc[mt][j][3]);
                if (domask) {
                    const int kg = kt * 64 + j * 8 + 2 * c4;
                    if (kg     > rgA) p0 = EMASK;
                    if (kg + 1 > rgA) p1 = EMASK;
                    if (kg     > rgB) p2 = EMASK;
                    if (kg + 1 > rgB) p3 = EMASK;
                }
                lsum[mt][0] += p0 + p1;
                lsum[mt][1] += p2 + p3;
                *(uint2*)&Psu[rl * ASW + j * 8 + 2 * c4] =
                    make_uint2(f2tf32(p0), f2tf32(p1));
                *(uint2*)&Psu[(rl + 8) * ASW + j * 8 + 2 * c4] =
                    make_uint2(f2tf32(p2), f2tf32(p3));
            }
        }
        __syncwarp();   // P rows are warp-private; order STS before LDSM

        // O += P V : A = P[32 q x 64 key], B = V^T via Vt[d][key]
        #pragma unroll
        for (int ks = 0; ks < 8; ++ks) {
            const int k0 = ks * 8;
            uint32_t af[2][4], bf[8][2];
            #pragma unroll
            for (int mt = 0; mt < 2; ++mt)
                ldsm4(af[mt], sP + (uint32_t)((w * 32 + mt * 16 + ar) * ASW + k0 + ac) * 4u);
            #pragma unroll
            for (int jp = 0; jp < 4; ++jp) {
                uint32_t r[4];
                ldsm4(r, sV + (uint32_t)((jp * 16 + br) * ASW + k0 + bc) * 4u);
                bf[2 * jp][0] = r[0]; bf[2 * jp][1] = r[1];
                bf[2 * jp + 1][0] = r[2]; bf[2 * jp + 1][1] = r[3];
            }
            #pragma unroll
            for (int mt = 0; mt < 2; ++mt)
                #pragma unroll
                for (int j = 0; j < 8; ++j)
                    mma8(oacc[mt][j], af[mt], bf[j]);
        }
        __syncthreads();   // protect Ks/Vt before next tile load
    }

    // Tail: strictly-future keys, uniform weight EMASK * suffix V sum
    const int nmask = TLEN - 64 * (ktmax + 1);
    for (int d = tid; d < HS; d += 128)
        Ks[d] = g_vsuf[((size_t)bh * (NT64 + 1) + ktmax + 1) * HS + d];
    __syncthreads();

    #pragma unroll
    for (int mt = 0; mt < 2; ++mt) {
        float lA = lsum[mt][0], lB = lsum[mt][1];
        lA += __shfl_xor_sync(0xffffffffu, lA, 1);
        lA += __shfl_xor_sync(0xffffffffu, lA, 2);
        lB += __shfl_xor_sync(0xffffffffu, lB, 1);
        lB += __shfl_xor_sync(0xffffffffu, lB, 2);
        const float invA = 1.0f / (lA + (float)nmask * EMASK);
        const float invB = 1.0f / (lB + (float)nmask * EMASK);

        const int rowA = b * TLEN + q0 + w * 32 + mt * 16 + qr;
        float* yA = y + (size_t)rowA * NEMBD + h * HS;
        float* yB = y + (size_t)(rowA + 8) * NEMBD + h * HS;
        #pragma unroll
        for (int j = 0; j < 8; ++j) {
            const int d0 = j * 8 + 2 * c4;
            const float v0 = Ks[d0], v1 = Ks[d0 + 1];
            *(float2*)&yA[d0] = make_float2((oacc[mt][j][0] + EMASK * v0) * invA,
                                            (oacc[mt][j][1] + EMASK * v1) * invA);
            *(float2*)&yB[d0] = make_float2((oacc[mt][j][2] + EMASK * v0) * invB,
                                            (oacc[mt][j][3] + EMASK * v1) * invB);
        }
    }
}

// ---------------------------------------------------------------------------
extern "C" void kernel_launch(void* const* d_in, const int* in_sizes, int n_in,
                              void* d_out, int out_size)
{
    const float* x      = (const float*)d_in[0];
    const float* w_attn = (const float*)d_in[1];
    const float* w_proj = (const float*)d_in[2];
    float* out = (float*)d_out;

    float *qkv, *y;
    cudaGetSymbolAddress((void**)&qkv, g_qkv);
    cudaGetSymbolAddress((void**)&y,   g_y);

    const int attn_smem = 384 * ASW * (int)sizeof(float);   // 104448 B
    cudaFuncSetAttribute(attn_mma, cudaFuncAttributeMaxDynamicSharedMemorySize,
                         attn_smem);

    // 1) QKV projection
    gemm_tf32<<<dim3(C3 / 128, BT / 128), 256>>>(x, w_attn, qkv, BT, C3, NEMBD);

    // 2) V suffix sums
    vsuf_partial<<<dim3(NT64, NBH), 64>>>(qkv);
    vsuf_suffix<<<NBH, 64>>>();

    // 3) Attention (causal part + closed-form masked tail)
    attn_mma<<<dim3(TLEN / 128, NBH), 128, attn_smem>>>(qkv, y);

    // 4) Output projection
    gemm_tf32<<<dim3(NEMBD / 128, BT / 128), 256>>>(y, w_proj, out, BT, NEMBD, NEMBD);
}